// round 2
// baseline (speedup 1.0000x reference)
#include <cuda_runtime.h>
#include <math.h>

#define NC 64
#define NNODE 50000
#define NEDGE 800000

// ---- scratch (allocation-free: __device__ globals) ----
__device__ __align__(16) float g_v   [NNODE * NC];
__device__ __align__(16) float g_asrc[NNODE * NC];
__device__ __align__(16) float g_adst[NNODE * NC];
__device__ __align__(16) float g_sum [NNODE * NC];
__device__ __align__(16) float g_acc [NNODE * NC];

// ---------------- K0: zero accumulators ----------------
__global__ void k_zero() {
    int i = blockIdx.x * blockDim.x + threadIdx.x;
    float4 z = make_float4(0.f, 0.f, 0.f, 0.f);
    if (i < NNODE * NC / 4) {
        reinterpret_cast<float4*>(g_sum)[i] = z;
        reinterpret_cast<float4*>(g_acc)[i] = z;
    }
}

// ---------------- K1: node projections ----------------
// h = relu(x@W_in + b_in); v = h@W_lin; a_src = h@W_src; a_dst = h@W_dst
// Block = 256 threads handles a 64-node tile. thread: c = tid&63, q = tid>>6
__global__ __launch_bounds__(256) void k_node(
    const float* __restrict__ x,
    const float* __restrict__ W_in, const float* __restrict__ b_in,
    const float* __restrict__ W_lin, const float* __restrict__ W_src,
    const float* __restrict__ W_dst, int n)
{
    __shared__ float A[64 * 64];   // x tile, then h tile
    __shared__ float B[64 * 64];   // current weight matrix
    const int tid = threadIdx.x;
    const int n0 = blockIdx.x * 64;
    const int c = tid & 63, q = tid >> 6;

    for (int i = tid; i < 4096; i += 256) {
        int nn = i >> 6;
        A[i] = (n0 + nn < n) ? x[(size_t)(n0 + nn) * 64 + (i & 63)] : 0.f;
        B[i] = W_in[i];
    }
    __syncthreads();

    float breg[64];
    #pragma unroll
    for (int k = 0; k < 64; k++) breg[k] = B[k * 64 + c];
    const float bc = b_in[c];

    float hreg[16];
    #pragma unroll
    for (int nn = 0; nn < 16; nn++) {
        const float4* ar = reinterpret_cast<const float4*>(&A[(q * 16 + nn) * 64]);
        float a0 = bc, a1 = 0.f, a2 = 0.f, a3 = 0.f;
        #pragma unroll
        for (int k4 = 0; k4 < 16; k4++) {
            float4 av = ar[k4];
            a0 = fmaf(av.x, breg[k4 * 4 + 0], a0);
            a1 = fmaf(av.y, breg[k4 * 4 + 1], a1);
            a2 = fmaf(av.z, breg[k4 * 4 + 2], a2);
            a3 = fmaf(av.w, breg[k4 * 4 + 3], a3);
        }
        hreg[nn] = fmaxf(0.f, (a0 + a1) + (a2 + a3));
    }
    __syncthreads();
    #pragma unroll
    for (int nn = 0; nn < 16; nn++) A[(q * 16 + nn) * 64 + c] = hreg[nn];

    const float* Ws[3] = { W_lin, W_src, W_dst };
    float*       Gs[3] = { g_v, g_asrc, g_adst };
    #pragma unroll
    for (int m = 0; m < 3; m++) {
        __syncthreads();
        for (int i = tid; i < 4096; i += 256) B[i] = Ws[m][i];
        __syncthreads();
        #pragma unroll
        for (int k = 0; k < 64; k++) breg[k] = B[k * 64 + c];
        #pragma unroll
        for (int nn = 0; nn < 16; nn++) {
            const float4* ar = reinterpret_cast<const float4*>(&A[(q * 16 + nn) * 64]);
            float a0 = 0.f, a1 = 0.f, a2 = 0.f, a3 = 0.f;
            #pragma unroll
            for (int k4 = 0; k4 < 16; k4++) {
                float4 av = ar[k4];
                a0 = fmaf(av.x, breg[k4 * 4 + 0], a0);
                a1 = fmaf(av.y, breg[k4 * 4 + 1], a1);
                a2 = fmaf(av.z, breg[k4 * 4 + 2], a2);
                a3 = fmaf(av.w, breg[k4 * 4 + 3], a3);
            }
            int ng = n0 + q * 16 + nn;
            if (ng < n) Gs[m][(size_t)ng * 64 + c] = (a0 + a1) + (a2 + a3);
        }
    }
}

// ---------------- K2: fused edge kernel ----------------
// per edge e (one thread each):
//   rel = pos[d]-pos[s]; p1 = relu(rel@Wp1+bp1); delta = p1@Wp2+bp2
//   alpha0 = a_dst[d]-a_src[s]+delta; t = relu(alpha0@Wa1+ba1)
//   alpha = t@Wa2+ba2; w = exp(alpha)
//   red: g_sum[d] += w ; g_acc[d] += w*(v[s]+delta)
// Weights live in shared (broadcast LDS.128); t[64] in registers;
// delta[64] in a per-thread shared column (conflict-free, allows dynamic c).
#define ETPB 128
__global__ __launch_bounds__(ETPB) void k_edge(
    const int* __restrict__ ei, const float* __restrict__ pos,
    const float* __restrict__ Wp1, const float* __restrict__ bp1,
    const float* __restrict__ Wp2, const float* __restrict__ bp2,
    const float* __restrict__ Wa1, const float* __restrict__ ba1,
    const float* __restrict__ Wa2, const float* __restrict__ ba2,
    int E, int ntiles)
{
    extern __shared__ float sm[];
    float* Wp2T   = sm;            // [c][h] = Wp2[h][c]
    float* Wa1s   = sm + 4096;     // [c][h] direct
    float* Wa2T   = sm + 8192;     // [c][h] = Wa2[h][c]
    float* Wp1s   = sm + 12288;    // [3][64]
    float* bp1s   = sm + 12480;
    float* bp2s   = sm + 12544;
    float* ba1s   = sm + 12608;
    float* ba2s   = sm + 12672;
    float* sdelta = sm + 12736;    // [64][ETPB]
    const int tid = threadIdx.x;

    for (int i = tid; i < 4096; i += ETPB) {
        int h = i >> 6, c = i & 63;
        Wp2T[c * 64 + h] = Wp2[i];
        Wa2T[c * 64 + h] = Wa2[i];
        Wa1s[i] = Wa1[i];
    }
    for (int i = tid; i < 192; i += ETPB) Wp1s[i] = Wp1[i];
    if (tid < 64) {
        bp1s[tid] = bp1[tid]; bp2s[tid] = bp2[tid];
        ba1s[tid] = ba1[tid]; ba2s[tid] = ba2[tid];
    }
    __syncthreads();

    for (int tile = blockIdx.x; tile < ntiles; tile += gridDim.x) {
        int e = tile * ETPB + tid;
        if (e >= E) continue;
        int s = ei[e], d = ei[E + e];

        float r0 = pos[d * 3 + 0] - pos[s * 3 + 0];
        float r1 = pos[d * 3 + 1] - pos[s * 3 + 1];
        float r2 = pos[d * 3 + 2] - pos[s * 3 + 2];

        // ---- pos_nn layer1 + layer2 -> delta (into shared column) ----
        {
            float p1v[64];
            #pragma unroll
            for (int h = 0; h < 64; h++)
                p1v[h] = fmaxf(0.f,
                    fmaf(r0, Wp1s[h], fmaf(r1, Wp1s[64 + h],
                    fmaf(r2, Wp1s[128 + h], bp1s[h]))));
            for (int c = 0; c < 64; c++) {
                const float4* w4 = reinterpret_cast<const float4*>(Wp2T + c * 64);
                float a0 = 0.f, a1 = 0.f, a2 = 0.f, a3 = 0.f;
                #pragma unroll
                for (int k = 0; k < 16; k++) {
                    float4 w = w4[k];
                    a0 = fmaf(p1v[4 * k + 0], w.x, a0);
                    a1 = fmaf(p1v[4 * k + 1], w.y, a1);
                    a2 = fmaf(p1v[4 * k + 2], w.z, a2);
                    a3 = fmaf(p1v[4 * k + 3], w.w, a3);
                }
                sdelta[c * ETPB + tid] = bp2s[c] + ((a0 + a1) + (a2 + a3));
            }
        }

        // ---- attn_nn layer1: t[h] = relu(sum_c alpha0[c]*Wa1[c][h] + ba1[h]) ----
        float tv[64];
        #pragma unroll
        for (int h = 0; h < 64; h++) tv[h] = 0.f;
        const float4* adp = reinterpret_cast<const float4*>(g_adst + (size_t)d * 64);
        const float4* asp = reinterpret_cast<const float4*>(g_asrc + (size_t)s * 64);
        for (int c4 = 0; c4 < 16; c4++) {
            float4 ad = adp[c4], as_ = asp[c4];
            float a00 = ad.x - as_.x + sdelta[(c4 * 4 + 0) * ETPB + tid];
            float a01 = ad.y - as_.y + sdelta[(c4 * 4 + 1) * ETPB + tid];
            float a02 = ad.z - as_.z + sdelta[(c4 * 4 + 2) * ETPB + tid];
            float a03 = ad.w - as_.w + sdelta[(c4 * 4 + 3) * ETPB + tid];
            #pragma unroll
            for (int j = 0; j < 4; j++) {
                float a0v = (j == 0) ? a00 : (j == 1) ? a01 : (j == 2) ? a02 : a03;
                const float4* w4 = reinterpret_cast<const float4*>(Wa1s + (c4 * 4 + j) * 64);
                #pragma unroll
                for (int k = 0; k < 16; k++) {
                    float4 w = w4[k];
                    tv[4 * k + 0] = fmaf(a0v, w.x, tv[4 * k + 0]);
                    tv[4 * k + 1] = fmaf(a0v, w.y, tv[4 * k + 1]);
                    tv[4 * k + 2] = fmaf(a0v, w.z, tv[4 * k + 2]);
                    tv[4 * k + 3] = fmaf(a0v, w.w, tv[4 * k + 3]);
                }
            }
        }
        #pragma unroll
        for (int h = 0; h < 64; h++) tv[h] = fmaxf(0.f, tv[h] + ba1s[h]);

        // ---- attn_nn layer2 + exp + reductions ----
        const float4* vp = reinterpret_cast<const float4*>(g_v + (size_t)s * 64);
        float* sump = g_sum + (size_t)d * 64;
        float* accp = g_acc + (size_t)d * 64;
        for (int c4 = 0; c4 < 16; c4++) {
            float4 vv = vp[c4];
            float wv[4], cv[4];
            #pragma unroll
            for (int j = 0; j < 4; j++) {
                int c = c4 * 4 + j;
                const float4* w4 = reinterpret_cast<const float4*>(Wa2T + c * 64);
                float a0 = 0.f, a1 = 0.f, a2 = 0.f, a3 = 0.f;
                #pragma unroll
                for (int k = 0; k < 16; k++) {
                    float4 w = w4[k];
                    a0 = fmaf(tv[4 * k + 0], w.x, a0);
                    a1 = fmaf(tv[4 * k + 1], w.y, a1);
                    a2 = fmaf(tv[4 * k + 2], w.z, a2);
                    a3 = fmaf(tv[4 * k + 3], w.w, a3);
                }
                float al = ba2s[c] + ((a0 + a1) + (a2 + a3));
                float ex = __expf(al);
                wv[j] = ex;
                float vj = (j == 0) ? vv.x : (j == 1) ? vv.y : (j == 2) ? vv.z : vv.w;
                cv[j] = ex * (vj + sdelta[c * ETPB + tid]);
            }
            asm volatile("red.global.add.v4.f32 [%0], {%1,%2,%3,%4};"
                :: "l"(sump + c4 * 4), "f"(wv[0]), "f"(wv[1]), "f"(wv[2]), "f"(wv[3])
                : "memory");
            asm volatile("red.global.add.v4.f32 [%0], {%1,%2,%3,%4};"
                :: "l"(accp + c4 * 4), "f"(cv[0]), "f"(cv[1]), "f"(cv[2]), "f"(cv[3])
                : "memory");
        }
    }
}

// ---------------- K3: normalize + output GEMM + ReLU ----------------
__global__ __launch_bounds__(256) void k_out(
    const float* __restrict__ W_out, const float* __restrict__ b_out,
    float* __restrict__ out, int n)
{
    __shared__ float A[64 * 64];
    __shared__ float B[64 * 64];
    const int tid = threadIdx.x;
    const int n0 = blockIdx.x * 64;
    const int c = tid & 63, q = tid >> 6;

    for (int i = tid; i < 4096; i += 256) {
        int nn = i >> 6;
        float acc = 0.f, s = 0.f;
        if (n0 + nn < n) {
            size_t gi = (size_t)(n0 + nn) * 64 + (i & 63);
            acc = g_acc[gi];
            s   = g_sum[gi];
        }
        A[i] = acc / (s + 1e-16f);
        B[i] = W_out[i];
    }
    __syncthreads();

    float breg[64];
    #pragma unroll
    for (int k = 0; k < 64; k++) breg[k] = B[k * 64 + c];
    const float bc = b_out[c];
    #pragma unroll
    for (int nn = 0; nn < 16; nn++) {
        const float4* ar = reinterpret_cast<const float4*>(&A[(q * 16 + nn) * 64]);
        float a0 = bc, a1 = 0.f, a2 = 0.f, a3 = 0.f;
        #pragma unroll
        for (int k4 = 0; k4 < 16; k4++) {
            float4 av = ar[k4];
            a0 = fmaf(av.x, breg[k4 * 4 + 0], a0);
            a1 = fmaf(av.y, breg[k4 * 4 + 1], a1);
            a2 = fmaf(av.z, breg[k4 * 4 + 2], a2);
            a3 = fmaf(av.w, breg[k4 * 4 + 3], a3);
        }
        int ng = n0 + q * 16 + nn;
        if (ng < n) out[(size_t)ng * 64 + c] = fmaxf(0.f, (a0 + a1) + (a2 + a3));
    }
}

// ---------------- launch ----------------
extern "C" void kernel_launch(void* const* d_in, const int* in_sizes, int n_in,
                              void* d_out, int out_size)
{
    const float* x     = (const float*)d_in[0];
    const float* pos   = (const float*)d_in[1];
    const int*   ei    = (const int*)  d_in[2];
    const float* W_in  = (const float*)d_in[3];
    const float* b_in  = (const float*)d_in[4];
    const float* W_lin = (const float*)d_in[5];
    const float* W_src = (const float*)d_in[6];
    const float* W_dst = (const float*)d_in[7];
    const float* Wp1   = (const float*)d_in[8];
    const float* bp1   = (const float*)d_in[9];
    const float* Wp2   = (const float*)d_in[10];
    const float* bp2   = (const float*)d_in[11];
    const float* Wa1   = (const float*)d_in[12];
    const float* ba1   = (const float*)d_in[13];
    const float* Wa2   = (const float*)d_in[14];
    const float* ba2   = (const float*)d_in[15];
    const float* W_out = (const float*)d_in[16];
    const float* b_out = (const float*)d_in[17];
    float* out = (float*)d_out;

    const int n = in_sizes[0] / NC;
    const int E = in_sizes[2] / 2;

    const int smem_edge = (12736 + 64 * ETPB) * (int)sizeof(float);  // 83712 B
    cudaFuncSetAttribute(k_edge, cudaFuncAttributeMaxDynamicSharedMemorySize, smem_edge);

    k_zero<<<(NNODE * NC / 4 + 255) / 256, 256>>>();
    k_node<<<(n + 63) / 64, 256>>>(x, W_in, b_in, W_lin, W_src, W_dst, n);

    const int ntiles = (E + ETPB - 1) / ETPB;
    int nblk = ntiles < 304 ? ntiles : 304;   // ~2 blocks/SM persistent
    k_edge<<<nblk, ETPB, smem_edge>>>(ei, pos, Wp1, bp1, Wp2, bp2,
                                      Wa1, ba1, Wa2, ba2, E, ntiles);

    k_out<<<(n + 63) / 64, 256>>>(W_out, b_out, out, n);
}

// round 4
// speedup vs baseline: 1.0240x; 1.0240x over previous
#include <cuda_runtime.h>
#include <math.h>

typedef unsigned long long u64;

#define NC 64
#define NNODE 50000
#define ETPB 192

// ---- scratch (allocation-free: __device__ globals) ----
__device__ __align__(16) float g_v   [NNODE * NC];
__device__ __align__(16) float g_asrc[NNODE * NC];
__device__ __align__(16) float g_adst[NNODE * NC];
__device__ __align__(16) float g_sum [NNODE * NC];
__device__ __align__(16) float g_acc [NNODE * NC];

// ---- packed fp32x2 helpers (Blackwell) ----
__device__ __forceinline__ u64 pk2(float a, float b) {
    u64 r; asm("mov.b64 %0, {%1, %2};" : "=l"(r) : "f"(a), "f"(b)); return r;
}
__device__ __forceinline__ u64 dup2(float v) { return pk2(v, v); }
__device__ __forceinline__ void unpk(u64 p, float& a, float& b) {
    asm("mov.b64 {%0, %1}, %2;" : "=f"(a), "=f"(b) : "l"(p));
}
__device__ __forceinline__ u64 ffma2(u64 a, u64 b, u64 c) {
    u64 d; asm("fma.rn.f32x2 %0, %1, %2, %3;" : "=l"(d) : "l"(a), "l"(b), "l"(c)); return d;
}
__device__ __forceinline__ u64 fadd2(u64 a, u64 b) {
    u64 d; asm("add.rn.f32x2 %0, %1, %2;" : "=l"(d) : "l"(a), "l"(b)); return d;
}

// ---------------- K0: zero accumulators ----------------
__global__ void k_zero() {
    int i = blockIdx.x * blockDim.x + threadIdx.x;
    float4 z = make_float4(0.f, 0.f, 0.f, 0.f);
    if (i < NNODE * NC / 4) {
        reinterpret_cast<float4*>(g_sum)[i] = z;
        reinterpret_cast<float4*>(g_acc)[i] = z;
    }
}

// ---------------- K1: node projections (f32x2) ----------------
// Tile: 64 nodes per block, 256 threads. c = tid&63, g = tid>>6.
// Activation tile stored TRANSPOSED with stride 66 floats: AT[k][n] at k*66+n,
// so a node-pair (2p,2p+1) is a single aligned u64 at ATu[k*33+p] (broadcast read).
__global__ __launch_bounds__(256) void k_node(
    const float* __restrict__ x,
    const float* __restrict__ W_in, const float* __restrict__ b_in,
    const float* __restrict__ W_lin, const float* __restrict__ W_src,
    const float* __restrict__ W_dst, int n)
{
    __shared__ float AT[64 * 66];
    __shared__ float Bsh[64 * 64];
    const int tid = threadIdx.x;
    const int n0 = blockIdx.x * 64;
    const int c = tid & 63, g = tid >> 6;

    for (int i = tid; i < 4096; i += 256) {
        int nn = i >> 6, cc = i & 63;
        AT[cc * 66 + nn] = (n0 + nn < n) ? x[(size_t)(n0 + nn) * 64 + cc] : 0.f;
        Bsh[i] = W_in[i];
    }
    __syncthreads();

    u64* ATu = reinterpret_cast<u64*>(AT);

    // GEMM1: h = relu(x@W_in + b_in), written back transposed into AT
    {
        u64 acc[8];
        u64 bi = dup2(b_in[c]);
        #pragma unroll
        for (int i = 0; i < 8; i++) acc[i] = bi;
        #pragma unroll 1
        for (int k = 0; k < 64; k++) {
            u64 bd = dup2(Bsh[k * 64 + c]);
            const u64* arow = ATu + k * 33 + g * 8;
            #pragma unroll
            for (int i = 0; i < 8; i++) acc[i] = ffma2(arow[i], bd, acc[i]);
        }
        __syncthreads();
        #pragma unroll
        for (int i = 0; i < 8; i++) {
            float f0, f1; unpk(acc[i], f0, f1);
            ATu[c * 33 + g * 8 + i] = pk2(fmaxf(f0, 0.f), fmaxf(f1, 0.f));
        }
        __syncthreads();
    }

    auto do_gemm = [&](const float* __restrict__ W, float* __restrict__ G) {
        for (int i = tid; i < 4096; i += 256) Bsh[i] = W[i];
        __syncthreads();
        u64 acc[8];
        #pragma unroll
        for (int i = 0; i < 8; i++) acc[i] = 0ull;
        #pragma unroll 1
        for (int k = 0; k < 64; k++) {
            u64 bd = dup2(Bsh[k * 64 + c]);
            const u64* arow = ATu + k * 33 + g * 8;
            #pragma unroll
            for (int i = 0; i < 8; i++) acc[i] = ffma2(arow[i], bd, acc[i]);
        }
        #pragma unroll
        for (int i = 0; i < 8; i++) {
            float f0, f1; unpk(acc[i], f0, f1);
            int nn = 16 * g + 2 * i;
            if (n0 + nn < n)     G[(size_t)(n0 + nn) * 64 + c] = f0;
            if (n0 + nn + 1 < n) G[(size_t)(n0 + nn + 1) * 64 + c] = f1;
        }
        __syncthreads();
    };
    do_gemm(W_lin, g_v);
    do_gemm(W_src, g_asrc);
    do_gemm(W_dst, g_adst);
}

// ---------------- K2: fused edge kernel (f32x2) ----------------
// One edge per thread. All three 64x64 matvecs use packed f32x2 FMA with
// channel-pair (or h-pair) accumulators. delta lives in a per-thread shared
// column (u64 pairs); t stays in registers (32 u64).
__global__ __launch_bounds__(ETPB, 2) void k_edge(
    const int* __restrict__ ei, const float* __restrict__ pos,
    const float* __restrict__ Wp1, const float* __restrict__ bp1,
    const float* __restrict__ Wp2, const float* __restrict__ bp2,
    const float* __restrict__ Wa1, const float* __restrict__ ba1,
    const float* __restrict__ Wa2, const float* __restrict__ ba2,
    int E, int ntiles)
{
    extern __shared__ float sm[];
    float* Wp2s = sm;            // [h][c] natural
    float* Wa1s = sm + 4096;     // [c][h] natural
    float* Wa2T = sm + 8192;     // [c][h] = Wa2[h][c] transposed
    float* Wp1s = sm + 12288;    // [3][64]
    float* bp1s = sm + 12480;
    float* bp2s = sm + 12544;
    float* ba1s = sm + 12608;
    float* ba2s = sm + 12672;
    u64*  sdel  = reinterpret_cast<u64*>(sm + 12736);  // [32][ETPB] u64 pairs
    const int tid = threadIdx.x;

    for (int i = tid; i < 4096; i += ETPB) {
        int h = i >> 6, cc = i & 63;
        Wp2s[i] = Wp2[i];
        Wa1s[i] = Wa1[i];
        Wa2T[cc * 64 + h] = Wa2[i];
    }
    for (int i = tid; i < 192; i += ETPB) Wp1s[i] = Wp1[i];
    if (tid < 64) {
        bp1s[tid] = bp1[tid]; bp2s[tid] = bp2[tid];
        ba1s[tid] = ba1[tid]; ba2s[tid] = ba2[tid];
    }
    __syncthreads();

    const float* df = reinterpret_cast<const float*>(sdel);

    for (int tile = blockIdx.x; tile < ntiles; tile += gridDim.x) {
        int e = tile * ETPB + tid;
        if (e >= E) continue;
        int s = ei[e], d = ei[E + e];

        float r0 = pos[d * 3 + 0] - pos[s * 3 + 0];
        float r1 = pos[d * 3 + 1] - pos[s * 3 + 1];
        float r2 = pos[d * 3 + 2] - pos[s * 3 + 2];

        // ---- GEMM1: delta = relu(rel@Wp1+bp1)@Wp2 + bp2 ----
        {
            u64 acc[32];
            const u64* bp2u = reinterpret_cast<const u64*>(bp2s);
            #pragma unroll
            for (int i = 0; i < 32; i++) acc[i] = bp2u[i];
            #pragma unroll 1
            for (int k = 0; k < 64; k++) {
                float p = fmaf(r2, Wp1s[128 + k], bp1s[k]);
                p = fmaf(r1, Wp1s[64 + k], p);
                p = fmaf(r0, Wp1s[k], p);
                p = fmaxf(p, 0.f);
                u64 pd = dup2(p);
                const ulonglong2* wr = reinterpret_cast<const ulonglong2*>(Wp2s + k * 64);
                #pragma unroll
                for (int i = 0; i < 16; i++) {
                    ulonglong2 w = wr[i];
                    acc[2 * i]     = ffma2(pd, w.x, acc[2 * i]);
                    acc[2 * i + 1] = ffma2(pd, w.y, acc[2 * i + 1]);
                }
            }
            u64* myd = sdel + tid;
            #pragma unroll
            for (int i = 0; i < 32; i++) myd[i * ETPB] = acc[i];
        }

        // ---- GEMM2: t = relu((a_dst[d]-a_src[s]+delta)@Wa1 + ba1), t in regs ----
        u64 t2[32];
        {
            const u64* ba1u = reinterpret_cast<const u64*>(ba1s);
            #pragma unroll
            for (int i = 0; i < 32; i++) t2[i] = ba1u[i];
            const float4* adp = reinterpret_cast<const float4*>(g_adst + (size_t)d * 64);
            const float4* asp = reinterpret_cast<const float4*>(g_asrc + (size_t)s * 64);
            float4 ad = adp[0], as0 = asp[0];
            #pragma unroll 1
            for (int c4 = 0; c4 < 16; c4++) {
                float4 adn, asn;
                int nx = (c4 < 15) ? c4 + 1 : 15;
                adn = adp[nx]; asn = asp[nx];
                #pragma unroll
                for (int j = 0; j < 4; j++) {
                    int cc = 4 * c4 + j;
                    float dv = df[((cc >> 1) * ETPB + tid) * 2 + (cc & 1)];
                    float aj = (j == 0) ? ad.x : (j == 1) ? ad.y : (j == 2) ? ad.z : ad.w;
                    float sj = (j == 0) ? as0.x : (j == 1) ? as0.y : (j == 2) ? as0.z : as0.w;
                    float al = (aj - sj) + dv;
                    u64 a2 = dup2(al);
                    const ulonglong2* wr = reinterpret_cast<const ulonglong2*>(Wa1s + cc * 64);
                    #pragma unroll
                    for (int i = 0; i < 16; i++) {
                        ulonglong2 w = wr[i];
                        t2[2 * i]     = ffma2(a2, w.x, t2[2 * i]);
                        t2[2 * i + 1] = ffma2(a2, w.y, t2[2 * i + 1]);
                    }
                }
                ad = adn; as0 = asn;
            }
            #pragma unroll
            for (int i = 0; i < 32; i++) {
                float f0, f1; unpk(t2[i], f0, f1);
                t2[i] = pk2(fmaxf(f0, 0.f), fmaxf(f1, 0.f));
            }
        }

        // ---- GEMM3: alpha = t@Wa2 + ba2 -> exp -> reductions ----
        {
            const float4* vp = reinterpret_cast<const float4*>(g_v + (size_t)s * 64);
            float* sump = g_sum + (size_t)d * 64;
            float* accp = g_acc + (size_t)d * 64;
            float4 vv = vp[0];
            #pragma unroll 1
            for (int c4 = 0; c4 < 16; c4++) {
                float4 vvn;
                int nx = (c4 < 15) ? c4 + 1 : 15;
                vvn = vp[nx];
                float wv[4], cv[4];
                #pragma unroll
                for (int j = 0; j < 4; j++) {
                    int cc = 4 * c4 + j;
                    const ulonglong2* wr = reinterpret_cast<const ulonglong2*>(Wa2T + cc * 64);
                    u64 ah[4] = {0ull, 0ull, 0ull, 0ull};
                    #pragma unroll
                    for (int i = 0; i < 16; i++) {
                        ulonglong2 w = wr[i];
                        ah[(2 * i) & 3]     = ffma2(t2[2 * i], w.x, ah[(2 * i) & 3]);
                        ah[(2 * i + 1) & 3] = ffma2(t2[2 * i + 1], w.y, ah[(2 * i + 1) & 3]);
                    }
                    u64 aa = fadd2(fadd2(ah[0], ah[1]), fadd2(ah[2], ah[3]));
                    float f0, f1; unpk(aa, f0, f1);
                    float al = f0 + f1 + ba2s[cc];
                    float ex = __expf(al);
                    wv[j] = ex;
                    float dv = df[((cc >> 1) * ETPB + tid) * 2 + (cc & 1)];
                    float vj = (j == 0) ? vv.x : (j == 1) ? vv.y : (j == 2) ? vv.z : vv.w;
                    cv[j] = ex * (vj + dv);
                }
                asm volatile("red.global.add.v4.f32 [%0], {%1,%2,%3,%4};"
                    :: "l"(sump + c4 * 4), "f"(wv[0]), "f"(wv[1]), "f"(wv[2]), "f"(wv[3])
                    : "memory");
                asm volatile("red.global.add.v4.f32 [%0], {%1,%2,%3,%4};"
                    :: "l"(accp + c4 * 4), "f"(cv[0]), "f"(cv[1]), "f"(cv[2]), "f"(cv[3])
                    : "memory");
                vv = vvn;
            }
        }
    }
}

// ---------------- K3: normalize + output GEMM + ReLU (f32x2) ----------------
__global__ __launch_bounds__(256) void k_out(
    const float* __restrict__ W_out, const float* __restrict__ b_out,
    float* __restrict__ out, int n)
{
    __shared__ float AT[64 * 66];
    __shared__ float Bsh[64 * 64];
    const int tid = threadIdx.x;
    const int n0 = blockIdx.x * 64;
    const int c = tid & 63, g = tid >> 6;

    for (int i = tid; i < 4096; i += 256) {
        int nn = i >> 6, cc = i & 63;
        float a = 0.f, s = 0.f;
        if (n0 + nn < n) {
            size_t gi = (size_t)(n0 + nn) * 64 + cc;
            a = g_acc[gi]; s = g_sum[gi];
        }
        AT[cc * 66 + nn] = a / (s + 1e-16f);
        Bsh[i] = W_out[i];
    }
    __syncthreads();

    u64* ATu = reinterpret_cast<u64*>(AT);
    u64 acc[8];
    u64 bi = dup2(b_out[c]);
    #pragma unroll
    for (int i = 0; i < 8; i++) acc[i] = bi;
    #pragma unroll 1
    for (int k = 0; k < 64; k++) {
        u64 bd = dup2(Bsh[k * 64 + c]);
        const u64* arow = ATu + k * 33 + g * 8;
        #pragma unroll
        for (int i = 0; i < 8; i++) acc[i] = ffma2(arow[i], bd, acc[i]);
    }
    #pragma unroll
    for (int i = 0; i < 8; i++) {
        float f0, f1; unpk(acc[i], f0, f1);
        int nn = 16 * g + 2 * i;
        if (n0 + nn < n)     out[(size_t)(n0 + nn) * 64 + c] = fmaxf(f0, 0.f);
        if (n0 + nn + 1 < n) out[(size_t)(n0 + nn + 1) * 64 + c] = fmaxf(f1, 0.f);
    }
}

// ---------------- launch ----------------
extern "C" void kernel_launch(void* const* d_in, const int* in_sizes, int n_in,
                              void* d_out, int out_size)
{
    const float* x     = (const float*)d_in[0];
    const float* pos   = (const float*)d_in[1];
    const int*   ei    = (const int*)  d_in[2];
    const float* W_in  = (const float*)d_in[3];
    const float* b_in  = (const float*)d_in[4];
    const float* W_lin = (const float*)d_in[5];
    const float* W_src = (const float*)d_in[6];
    const float* W_dst = (const float*)d_in[7];
    const float* Wp1   = (const float*)d_in[8];
    const float* bp1   = (const float*)d_in[9];
    const float* Wp2   = (const float*)d_in[10];
    const float* bp2   = (const float*)d_in[11];
    const float* Wa1   = (const float*)d_in[12];
    const float* ba1   = (const float*)d_in[13];
    const float* Wa2   = (const float*)d_in[14];
    const float* ba2   = (const float*)d_in[15];
    const float* W_out = (const float*)d_in[16];
    const float* b_out = (const float*)d_in[17];
    float* out = (float*)d_out;

    const int n = in_sizes[0] / NC;
    const int E = in_sizes[2] / 2;

    const int smem_edge = (12736 + 64 * ETPB) * (int)sizeof(float);  // 100096 B
    cudaFuncSetAttribute(k_edge, cudaFuncAttributeMaxDynamicSharedMemorySize, smem_edge);

    k_zero<<<(NNODE * NC / 4 + 255) / 256, 256>>>();
    k_node<<<(n + 63) / 64, 256>>>(x, W_in, b_in, W_lin, W_src, W_dst, n);

    const int ntiles = (E + ETPB - 1) / ETPB;
    int nblk = ntiles < 296 ? ntiles : 296;   // 2 persistent blocks/SM
    k_edge<<<nblk, ETPB, smem_edge>>>(ei, pos, Wp1, bp1, Wp2, bp2,
                                      Wa1, ba1, Wa2, ba2, E, ntiles);

    k_out<<<(n + 63) / 64, 256>>>(W_out, b_out, out, n);
}

// round 5
// speedup vs baseline: 2.1622x; 2.1116x over previous
#include <cuda_runtime.h>
#include <math.h>

typedef unsigned long long u64;
typedef unsigned int u32;

#define NC 64
#define NNODE 50000
#define WTPB 8          // warps per block in edge kernel

// ---- scratch (allocation-free: __device__ globals) ----
__device__ __align__(16) float g_v   [NNODE * NC];
__device__ __align__(16) float g_asrc[NNODE * NC];
__device__ __align__(16) float g_adst[NNODE * NC];
__device__ __align__(16) float g_sum [NNODE * NC];
__device__ __align__(16) float g_acc [NNODE * NC];

// ---- packed fp32x2 helpers (for node kernels) ----
__device__ __forceinline__ u64 pk2(float a, float b) {
    u64 r; asm("mov.b64 %0, {%1, %2};" : "=l"(r) : "f"(a), "f"(b)); return r;
}
__device__ __forceinline__ u64 dup2(float v) { return pk2(v, v); }
__device__ __forceinline__ void unpk(u64 p, float& a, float& b) {
    asm("mov.b64 {%0, %1}, %2;" : "=f"(a), "=f"(b) : "l"(p));
}
__device__ __forceinline__ u64 ffma2(u64 a, u64 b, u64 c) {
    u64 d; asm("fma.rn.f32x2 %0, %1, %2, %3;" : "=l"(d) : "l"(a), "l"(b), "l"(c)); return d;
}

// ---- tf32 helpers ----
__device__ __forceinline__ u32 f2tf(float f) {
    u32 u; asm("cvt.rna.tf32.f32 %0, %1;" : "=r"(u) : "f"(f)); return u;
}
__device__ __forceinline__ void mma8(float* c, u32 a0, u32 a1, u32 a2, u32 a3,
                                     u32 b0, u32 b1) {
    asm volatile(
        "mma.sync.aligned.m16n8k8.row.col.f32.tf32.tf32.f32 "
        "{%0,%1,%2,%3}, {%4,%5,%6,%7}, {%8,%9}, {%0,%1,%2,%3};"
        : "+f"(c[0]), "+f"(c[1]), "+f"(c[2]), "+f"(c[3])
        : "r"(a0), "r"(a1), "r"(a2), "r"(a3), "r"(b0), "r"(b1));
}

// ---------------- K0: zero accumulators ----------------
__global__ void k_zero() {
    int i = blockIdx.x * blockDim.x + threadIdx.x;
    float4 z = make_float4(0.f, 0.f, 0.f, 0.f);
    if (i < NNODE * NC / 4) {
        reinterpret_cast<float4*>(g_sum)[i] = z;
        reinterpret_cast<float4*>(g_acc)[i] = z;
    }
}

// ---------------- K1: node projections (f32x2) ----------------
__global__ __launch_bounds__(256) void k_node(
    const float* __restrict__ x,
    const float* __restrict__ W_in, const float* __restrict__ b_in,
    const float* __restrict__ W_lin, const float* __restrict__ W_src,
    const float* __restrict__ W_dst, int n)
{
    __shared__ float AT[64 * 66];
    __shared__ float Bsh[64 * 64];
    const int tid = threadIdx.x;
    const int n0 = blockIdx.x * 64;
    const int c = tid & 63, g = tid >> 6;

    for (int i = tid; i < 4096; i += 256) {
        int nn = i >> 6, cc = i & 63;
        AT[cc * 66 + nn] = (n0 + nn < n) ? x[(size_t)(n0 + nn) * 64 + cc] : 0.f;
        Bsh[i] = W_in[i];
    }
    __syncthreads();

    u64* ATu = reinterpret_cast<u64*>(AT);

    {
        u64 acc[8];
        u64 bi = dup2(b_in[c]);
        #pragma unroll
        for (int i = 0; i < 8; i++) acc[i] = bi;
        #pragma unroll 1
        for (int k = 0; k < 64; k++) {
            u64 bd = dup2(Bsh[k * 64 + c]);
            const u64* arow = ATu + k * 33 + g * 8;
            #pragma unroll
            for (int i = 0; i < 8; i++) acc[i] = ffma2(arow[i], bd, acc[i]);
        }
        __syncthreads();
        #pragma unroll
        for (int i = 0; i < 8; i++) {
            float f0, f1; unpk(acc[i], f0, f1);
            ATu[c * 33 + g * 8 + i] = pk2(fmaxf(f0, 0.f), fmaxf(f1, 0.f));
        }
        __syncthreads();
    }

    auto do_gemm = [&](const float* __restrict__ W, float* __restrict__ G) {
        for (int i = tid; i < 4096; i += 256) Bsh[i] = W[i];
        __syncthreads();
        u64 acc[8];
        #pragma unroll
        for (int i = 0; i < 8; i++) acc[i] = 0ull;
        #pragma unroll 1
        for (int k = 0; k < 64; k++) {
            u64 bd = dup2(Bsh[k * 64 + c]);
            const u64* arow = ATu + k * 33 + g * 8;
            #pragma unroll
            for (int i = 0; i < 8; i++) acc[i] = ffma2(arow[i], bd, acc[i]);
        }
        #pragma unroll
        for (int i = 0; i < 8; i++) {
            float f0, f1; unpk(acc[i], f0, f1);
            int nn = 16 * g + 2 * i;
            if (n0 + nn < n)     G[(size_t)(n0 + nn) * 64 + c] = f0;
            if (n0 + nn + 1 < n) G[(size_t)(n0 + nn + 1) * 64 + c] = f1;
        }
        __syncthreads();
    };
    do_gemm(W_lin, g_v);
    do_gemm(W_src, g_asrc);
    do_gemm(W_dst, g_adst);
}

// ---------------- K2: fused edge kernel (tf32 mma.sync) ----------------
// Each warp owns a 16-edge m-tile. Three GEMMs (M=16,N=64,K=64) via
// m16n8k8 tf32 mma with fragment-prepacked weights in shared.
// Fragment coords (lane = 4*g' + t4): C rows {g', g'+8}, cols {8nt+2t4, +1}.
__global__ __launch_bounds__(32 * WTPB, 2) void k_edge(
    const int* __restrict__ ei, const float* __restrict__ pos,
    const float* __restrict__ Wp1, const float* __restrict__ bp1,
    const float* __restrict__ Wp2, const float* __restrict__ bp2,
    const float* __restrict__ Wa1, const float* __restrict__ ba1,
    const float* __restrict__ Wa2, const float* __restrict__ ba2,
    int E)
{
    extern __shared__ float sm[];
    float2* Wp2P = reinterpret_cast<float2*>(sm);          // 2048 float2
    float2* Wa1P = Wp2P + 2048;
    float2* Wa2P = Wa1P + 2048;
    float* Wp1s  = sm + 12288;                              // [3][64]
    float* bp1s  = Wp1s + 192;
    float* bp2s  = bp1s + 64;
    float* ba1s  = bp2s + 64;
    float* ba2s  = ba1s + 64;
    float* sA0b  = ba2s + 64;                               // 8 warps * [16][68]
    float* sRelb = sA0b + WTPB * 1088;                      // 8 * [16][4]
    int*   sSDb  = reinterpret_cast<int*>(sRelb + WTPB * 64); // 8 * 32 ints

    const int tid = threadIdx.x;

    // ---- prepack weights into B-fragment order (tf32) ----
    for (int i = tid; i < 2048; i += 32 * WTPB) {
        int ktnt = i >> 5, ln = i & 31;
        int kt = ktnt >> 3, nt = ktnt & 7;
        int lt4 = ln & 3, lg = ln >> 2;
        int r0 = (kt * 8 + lt4) * 64 + nt * 8 + lg;
        int r1 = (kt * 8 + lt4 + 4) * 64 + nt * 8 + lg;
        Wp2P[i] = make_float2(__uint_as_float(f2tf(Wp2[r0])), __uint_as_float(f2tf(Wp2[r1])));
        Wa1P[i] = make_float2(__uint_as_float(f2tf(Wa1[r0])), __uint_as_float(f2tf(Wa1[r1])));
        Wa2P[i] = make_float2(__uint_as_float(f2tf(Wa2[r0])), __uint_as_float(f2tf(Wa2[r1])));
    }
    for (int i = tid; i < 192; i += 32 * WTPB) Wp1s[i] = Wp1[i];
    if (tid < 64) {
        bp1s[tid] = bp1[tid]; bp2s[tid] = bp2[tid];
        ba1s[tid] = ba1[tid]; ba2s[tid] = ba2[tid];
    }
    __syncthreads();

    const int wid = tid >> 5, lane = tid & 31;
    const int g = lane >> 2, t4 = lane & 3;
    float* sA0  = sA0b + wid * 1088;     // [16][68]
    float* sRel = sRelb + wid * 64;      // [16][4]
    int*   sS   = sSDb + wid * 32;
    int*   sD   = sS + 16;

    const int ntile = (E + 15) >> 4;
    const int nwarp = gridDim.x * WTPB;

    for (int tile = blockIdx.x * WTPB + wid; tile < ntile; tile += nwarp) {
        const int e0 = tile * 16;

        // ---- load edge endpoints + rel positions (lanes 0-15) ----
        if (lane < 16) {
            int e = e0 + lane;
            int s = 0, d = 0;
            float r0 = 0.f, r1 = 0.f, r2 = 0.f;
            if (e < E) {
                s = ei[e]; d = ei[E + e];
                r0 = pos[d * 3 + 0] - pos[s * 3 + 0];
                r1 = pos[d * 3 + 1] - pos[s * 3 + 1];
                r2 = pos[d * 3 + 2] - pos[s * 3 + 2];
            }
            sS[lane] = s; sD[lane] = d;
            sRel[lane * 4 + 0] = r0; sRel[lane * 4 + 1] = r1; sRel[lane * 4 + 2] = r2;
        }
        __syncwarp();

        const float rA0 = sRel[g * 4 + 0], rA1 = sRel[g * 4 + 1], rA2 = sRel[g * 4 + 2];
        const float rB0 = sRel[(g + 8) * 4 + 0], rB1 = sRel[(g + 8) * 4 + 1], rB2 = sRel[(g + 8) * 4 + 2];

        // ---- GEMM1: delta = relu(rel@Wp1+bp1)@Wp2 + bp2, frags in dl ----
        float dl[8][4];
        #pragma unroll
        for (int nt = 0; nt < 8; nt++) {
            float b0 = bp2s[nt * 8 + 2 * t4], b1 = bp2s[nt * 8 + 2 * t4 + 1];
            dl[nt][0] = b0; dl[nt][1] = b1; dl[nt][2] = b0; dl[nt][3] = b1;
        }
        #pragma unroll
        for (int kt = 0; kt < 8; kt++) {
            int h0 = 8 * kt + t4, h1 = h0 + 4;
            float w00 = Wp1s[h0], w01 = Wp1s[64 + h0], w02 = Wp1s[128 + h0], bb0 = bp1s[h0];
            float w10 = Wp1s[h1], w11 = Wp1s[64 + h1], w12 = Wp1s[128 + h1], bb1 = bp1s[h1];
            float pA0 = fmaxf(0.f, fmaf(rA0, w00, fmaf(rA1, w01, fmaf(rA2, w02, bb0))));
            float pB0 = fmaxf(0.f, fmaf(rB0, w00, fmaf(rB1, w01, fmaf(rB2, w02, bb0))));
            float pA1 = fmaxf(0.f, fmaf(rA0, w10, fmaf(rA1, w11, fmaf(rA2, w12, bb1))));
            float pB1 = fmaxf(0.f, fmaf(rB0, w10, fmaf(rB1, w11, fmaf(rB2, w12, bb1))));
            u32 a0 = f2tf(pA0), a1 = f2tf(pB0), a2 = f2tf(pA1), a3 = f2tf(pB1);
            #pragma unroll
            for (int nt = 0; nt < 8; nt++) {
                float2 b = Wp2P[(kt * 8 + nt) * 32 + lane];
                mma8(dl[nt], a0, a1, a2, a3, __float_as_uint(b.x), __float_as_uint(b.y));
            }
        }

        // ---- store delta frags to sA0 ----
        #pragma unroll
        for (int nt = 0; nt < 8; nt++) {
            reinterpret_cast<float2*>(sA0 + g * 68)[nt * 4 + t4] = make_float2(dl[nt][0], dl[nt][1]);
            reinterpret_cast<float2*>(sA0 + (g + 8) * 68)[nt * 4 + t4] = make_float2(dl[nt][2], dl[nt][3]);
        }
        __syncwarp();

        // ---- gather adiff = a_dst[d]-a_src[s], add into sA0 (-> alpha0) ----
        {
            int er = lane & 15, half = lane >> 4;
            int e = e0 + er;
            if (e < E) {
                int s = sS[er], d = sD[er];
                const float4* ap = reinterpret_cast<const float4*>(g_adst + (size_t)d * 64) + half * 8;
                const float4* bp = reinterpret_cast<const float4*>(g_asrc + (size_t)s * 64) + half * 8;
                float* row = sA0 + er * 68 + half * 32;
                #pragma unroll
                for (int i = 0; i < 8; i++) {
                    float4 av = ap[i], bv = bp[i];
                    row[4 * i + 0] += av.x - bv.x;
                    row[4 * i + 1] += av.y - bv.y;
                    row[4 * i + 2] += av.z - bv.z;
                    row[4 * i + 3] += av.w - bv.w;
                }
            }
        }
        __syncwarp();

        // ---- GEMM2: t = relu(alpha0 @ Wa1 + ba1) ----
        float tt[8][4];
        #pragma unroll
        for (int nt = 0; nt < 8; nt++) {
            float b0 = ba1s[nt * 8 + 2 * t4], b1 = ba1s[nt * 8 + 2 * t4 + 1];
            tt[nt][0] = b0; tt[nt][1] = b1; tt[nt][2] = b0; tt[nt][3] = b1;
        }
        #pragma unroll
        for (int kt = 0; kt < 8; kt++) {
            u32 a0 = f2tf(sA0[g * 68 + 8 * kt + t4]);
            u32 a1 = f2tf(sA0[(g + 8) * 68 + 8 * kt + t4]);
            u32 a2 = f2tf(sA0[g * 68 + 8 * kt + t4 + 4]);
            u32 a3 = f2tf(sA0[(g + 8) * 68 + 8 * kt + t4 + 4]);
            #pragma unroll
            for (int nt = 0; nt < 8; nt++) {
                float2 b = Wa1P[(kt * 8 + nt) * 32 + lane];
                mma8(tt[nt], a0, a1, a2, a3, __float_as_uint(b.x), __float_as_uint(b.y));
            }
        }
        __syncwarp();
        // relu + store t to sA0
        #pragma unroll
        for (int nt = 0; nt < 8; nt++) {
            reinterpret_cast<float2*>(sA0 + g * 68)[nt * 4 + t4] =
                make_float2(fmaxf(tt[nt][0], 0.f), fmaxf(tt[nt][1], 0.f));
            reinterpret_cast<float2*>(sA0 + (g + 8) * 68)[nt * 4 + t4] =
                make_float2(fmaxf(tt[nt][2], 0.f), fmaxf(tt[nt][3], 0.f));
        }
        __syncwarp();

        // ---- GEMM3: alpha = t @ Wa2 + ba2 (reuse tt as accum) ----
        float al[8][4];
        #pragma unroll
        for (int nt = 0; nt < 8; nt++) {
            float b0 = ba2s[nt * 8 + 2 * t4], b1 = ba2s[nt * 8 + 2 * t4 + 1];
            al[nt][0] = b0; al[nt][1] = b1; al[nt][2] = b0; al[nt][3] = b1;
        }
        #pragma unroll
        for (int kt = 0; kt < 8; kt++) {
            u32 a0 = f2tf(sA0[g * 68 + 8 * kt + t4]);
            u32 a1 = f2tf(sA0[(g + 8) * 68 + 8 * kt + t4]);
            u32 a2 = f2tf(sA0[g * 68 + 8 * kt + t4 + 4]);
            u32 a3 = f2tf(sA0[(g + 8) * 68 + 8 * kt + t4 + 4]);
            #pragma unroll
            for (int nt = 0; nt < 8; nt++) {
                float2 b = Wa2P[(kt * 8 + nt) * 32 + lane];
                mma8(al[nt], a0, a1, a2, a3, __float_as_uint(b.x), __float_as_uint(b.y));
            }
        }

        // ---- epilogue: exp, weight by (v+delta), reduce ----
        const int sG = sS[g], dG = sD[g], sB = sS[g + 8], dB = sD[g + 8];
        const bool vG = (e0 + g) < E, vB = (e0 + g + 8) < E;
        #pragma unroll
        for (int nt = 0; nt < 8; nt++) {
            int c = nt * 8 + 2 * t4;
            if (vG) {
                float eg0 = __expf(al[nt][0]), eg1 = __expf(al[nt][1]);
                float2 v = *reinterpret_cast<const float2*>(g_v + (size_t)sG * 64 + c);
                float c0 = eg0 * (v.x + dl[nt][0]);
                float c1 = eg1 * (v.y + dl[nt][1]);
                asm volatile("red.global.add.v2.f32 [%0], {%1,%2};"
                    :: "l"(g_sum + (size_t)dG * 64 + c), "f"(eg0), "f"(eg1) : "memory");
                asm volatile("red.global.add.v2.f32 [%0], {%1,%2};"
                    :: "l"(g_acc + (size_t)dG * 64 + c), "f"(c0), "f"(c1) : "memory");
            }
            if (vB) {
                float eb0 = __expf(al[nt][2]), eb1 = __expf(al[nt][3]);
                float2 v = *reinterpret_cast<const float2*>(g_v + (size_t)sB * 64 + c);
                float c0 = eb0 * (v.x + dl[nt][2]);
                float c1 = eb1 * (v.y + dl[nt][3]);
                asm volatile("red.global.add.v2.f32 [%0], {%1,%2};"
                    :: "l"(g_sum + (size_t)dB * 64 + c), "f"(eb0), "f"(eb1) : "memory");
                asm volatile("red.global.add.v2.f32 [%0], {%1,%2};"
                    :: "l"(g_acc + (size_t)dB * 64 + c), "f"(c0), "f"(c1) : "memory");
            }
        }
    }
}

// ---------------- K3: normalize + output GEMM + ReLU (f32x2) ----------------
__global__ __launch_bounds__(256) void k_out(
    const float* __restrict__ W_out, const float* __restrict__ b_out,
    float* __restrict__ out, int n)
{
    __shared__ float AT[64 * 66];
    __shared__ float Bsh[64 * 64];
    const int tid = threadIdx.x;
    const int n0 = blockIdx.x * 64;
    const int c = tid & 63, g = tid >> 6;

    for (int i = tid; i < 4096; i += 256) {
        int nn = i >> 6, cc = i & 63;
        float a = 0.f, s = 0.f;
        if (n0 + nn < n) {
            size_t gi = (size_t)(n0 + nn) * 64 + cc;
            a = g_acc[gi]; s = g_sum[gi];
        }
        AT[cc * 66 + nn] = a / (s + 1e-16f);
        Bsh[i] = W_out[i];
    }
    __syncthreads();

    u64* ATu = reinterpret_cast<u64*>(AT);
    u64 acc[8];
    u64 bi = dup2(b_out[c]);
    #pragma unroll
    for (int i = 0; i < 8; i++) acc[i] = bi;
    #pragma unroll 1
    for (int k = 0; k < 64; k++) {
        u64 bd = dup2(Bsh[k * 64 + c]);
        const u64* arow = ATu + k * 33 + g * 8;
        #pragma unroll
        for (int i = 0; i < 8; i++) acc[i] = ffma2(arow[i], bd, acc[i]);
    }
    #pragma unroll
    for (int i = 0; i < 8; i++) {
        float f0, f1; unpk(acc[i], f0, f1);
        int nn = 16 * g + 2 * i;
        if (n0 + nn < n)     out[(size_t)(n0 + nn) * 64 + c] = fmaxf(f0, 0.f);
        if (n0 + nn + 1 < n) out[(size_t)(n0 + nn + 1) * 64 + c] = fmaxf(f1, 0.f);
    }
}

// ---------------- launch ----------------
extern "C" void kernel_launch(void* const* d_in, const int* in_sizes, int n_in,
                              void* d_out, int out_size)
{
    const float* x     = (const float*)d_in[0];
    const float* pos   = (const float*)d_in[1];
    const int*   ei    = (const int*)  d_in[2];
    const float* W_in  = (const float*)d_in[3];
    const float* b_in  = (const float*)d_in[4];
    const float* W_lin = (const float*)d_in[5];
    const float* W_src = (const float*)d_in[6];
    const float* W_dst = (const float*)d_in[7];
    const float* Wp1   = (const float*)d_in[8];
    const float* bp1   = (const float*)d_in[9];
    const float* Wp2   = (const float*)d_in[10];
    const float* bp2   = (const float*)d_in[11];
    const float* Wa1   = (const float*)d_in[12];
    const float* ba1   = (const float*)d_in[13];
    const float* Wa2   = (const float*)d_in[14];
    const float* ba2   = (const float*)d_in[15];
    const float* W_out = (const float*)d_in[16];
    const float* b_out = (const float*)d_in[17];
    float* out = (float*)d_out;

    const int n = in_sizes[0] / NC;
    const int E = in_sizes[2] / 2;

    // smem: 12288 (packed W) + 192 + 256 + 8*1088 + 8*64 + 8*32(int) floats
    const int smem_edge = (12288 + 192 + 256 + WTPB * 1088 + WTPB * 64 + WTPB * 32) * 4;
    cudaFuncSetAttribute(k_edge, cudaFuncAttributeMaxDynamicSharedMemorySize, smem_edge);

    k_zero<<<(NNODE * NC / 4 + 255) / 256, 256>>>();
    k_node<<<(n + 63) / 64, 256>>>(x, W_in, b_in, W_lin, W_src, W_dst, n);

    k_edge<<<296, 32 * WTPB, smem_edge>>>(ei, pos, Wp1, bp1, Wp2, bp2,
                                          Wa1, ba1, Wa2, ba2, E);

    k_out<<<(n + 63) / 64, 256>>>(W_out, b_out, out, n);
}